// round 1
// baseline (speedup 1.0000x reference)
#include <cuda_runtime.h>
#include <math.h>

#define SEQ 2048
#define BAT 128
#define INP 128
#define HID 128
#define GATES 512   // 4*HID

// 512 MB scratch for the precomputed input contribution xg[s][b][g]
__device__ float g_xg[(size_t)SEQ * BAT * GATES];

// ---------------------------------------------------------------------------
// Packed fp32x2 FMA (Blackwell): two full-precision fp32 FMAs per instruction.
// ---------------------------------------------------------------------------
__device__ __forceinline__ void fma2(unsigned long long& d,
                                     unsigned long long a,
                                     unsigned long long b) {
    asm("fma.rn.f32x2 %0, %1, %2, %0;" : "+l"(d) : "l"(a), "l"(b));
}
__device__ __forceinline__ float2 unpack2(unsigned long long v) {
    float2 r;
    asm("mov.b64 {%0, %1}, %2;" : "=f"(r.x), "=f"(r.y) : "l"(v));
    return r;
}

// ---------------------------------------------------------------------------
// Kernel A: xg[m][g] = sum_k x[m][k] * V[g][k] + b[g] + b2[g]
// M = SEQ*BAT = 262144, N = 512, K = 128 (single K tile).
// 128x128 block tile, 256 threads, 8x8 per-thread micro-tile, f32x2 math.
// smem: As[64 kpairs][128 m] float2 + Bs[64 kpairs][128 n] float2 = 128 KB.
// ---------------------------------------------------------------------------
__global__ __launch_bounds__(256, 1) void xg_kernel(
    const float* __restrict__ x, const float* __restrict__ V,
    const float* __restrict__ b1, const float* __restrict__ b2,
    float* __restrict__ xg)
{
    extern __shared__ unsigned char smraw[];
    float2* As = reinterpret_cast<float2*>(smraw);            // 64*128 float2
    float2* Bs = As + 64 * 128;                                // 64*128 float2

    const int tid = threadIdx.x;
    const int m0 = blockIdx.x * 128;
    const int n0 = blockIdx.y * 128;

    // Load tiles, interleaving k into pairs: As[k/2][m] = {x[m][k], x[m][k+1]}
    for (int idx = tid; idx < 128 * 32; idx += 256) {
        int row = idx >> 5;
        int k4  = (idx & 31) << 2;
        float4 xv = *reinterpret_cast<const float4*>(x + (size_t)(m0 + row) * INP + k4);
        As[(k4 >> 1) * 128 + row]       = make_float2(xv.x, xv.y);
        As[((k4 >> 1) + 1) * 128 + row] = make_float2(xv.z, xv.w);
        float4 vv = *reinterpret_cast<const float4*>(V + (size_t)(n0 + row) * INP + k4);
        Bs[(k4 >> 1) * 128 + row]       = make_float2(vv.x, vv.y);
        Bs[((k4 >> 1) + 1) * 128 + row] = make_float2(vv.z, vv.w);
    }
    __syncthreads();

    const int tx = tid & 15, ty = tid >> 4;
    const int mr = ty * 8, nr = tx * 8;

    unsigned long long acc[8][8];
#pragma unroll
    for (int i = 0; i < 8; i++)
#pragma unroll
        for (int j = 0; j < 8; j++) acc[i][j] = 0ULL;

#pragma unroll 2
    for (int kp = 0; kp < 64; kp++) {
        ulonglong2 Areg[4], Breg[4];
#pragma unroll
        for (int i = 0; i < 4; i++) {
            Areg[i] = *reinterpret_cast<const ulonglong2*>(&As[kp * 128 + mr + 2 * i]);
            Breg[i] = *reinterpret_cast<const ulonglong2*>(&Bs[kp * 128 + nr + 2 * i]);
        }
#pragma unroll
        for (int i = 0; i < 8; i++) {
            unsigned long long av = (i & 1) ? Areg[i >> 1].y : Areg[i >> 1].x;
#pragma unroll
            for (int j = 0; j < 8; j++) {
                unsigned long long bv = (j & 1) ? Breg[j >> 1].y : Breg[j >> 1].x;
                fma2(acc[i][j], av, bv);
            }
        }
    }

    float bias[8];
#pragma unroll
    for (int j = 0; j < 8; j++)
        bias[j] = b1[n0 + nr + j] + b2[n0 + nr + j];

#pragma unroll
    for (int i = 0; i < 8; i++) {
        float res[8];
#pragma unroll
        for (int j = 0; j < 8; j++) {
            float2 p = unpack2(acc[i][j]);
            res[j] = p.x + p.y + bias[j];
        }
        size_t base = (size_t)(m0 + mr + i) * GATES + n0 + nr;
        *reinterpret_cast<float4*>(xg + base)     = make_float4(res[0], res[1], res[2], res[3]);
        *reinterpret_cast<float4*>(xg + base + 4) = make_float4(res[4], res[5], res[6], res[7]);
    }
}

// ---------------------------------------------------------------------------
// Kernel B: the recurrence. One CTA per batch element, 512 threads.
// Thread t owns gate row t. Weights W[t][0..95] live in registers
// (24 x ulonglong2 = 96 floats), W[*][96..127] in smem (64 KB).
// h broadcast via smem; gates regrouped via smem; c/h state in threads t<128.
// ---------------------------------------------------------------------------
__global__ __launch_bounds__(512, 1) void lstm_rec_kernel(
    const float* __restrict__ xg, const float* __restrict__ W,
    float* __restrict__ out)
{
    extern __shared__ unsigned char smraw[];
    ulonglong2* WqS = reinterpret_cast<ulonglong2*>(smraw);     // [8][512] = 64 KB
    float* hs = reinterpret_cast<float*>(smraw + 8 * 512 * 16); // 128 floats
    float* gs = hs + 128;                                        // 512 floats

    const int t   = threadIdx.x;
    const int bat = blockIdx.x;

    // Register-resident weights: W[t][0..95] as 24 packed ulonglong2 (4 floats each)
    ulonglong2 wr[24];
    const ulonglong2* Wrow = reinterpret_cast<const ulonglong2*>(W + (size_t)t * INP);
#pragma unroll
    for (int q = 0; q < 24; q++) wr[q] = Wrow[q];

    // smem-resident weights: W[g][96 + 4*kq .. +3] for all g
    for (int idx = t; idx < 8 * 512; idx += 512) {
        int kq = idx >> 9;
        int g  = idx & 511;
        WqS[kq * 512 + g] =
            *reinterpret_cast<const ulonglong2*>(W + (size_t)g * INP + 96 + kq * 4);
    }
    if (t < HID) hs[t] = 0.0f;
    __syncthreads();

    float c = 0.0f, hlast = 0.0f;
    float xg_cur = xg[(size_t)bat * GATES + t];
    const ulonglong2* hs2 = reinterpret_cast<const ulonglong2*>(hs);

    for (int s = 0; s < SEQ; s++) {
        // prefetch next step's xg (hidden under the FMA loop)
        float xg_next = 0.0f;
        if (s + 1 < SEQ)
            xg_next = xg[((size_t)(s + 1) * BAT + bat) * GATES + t];

        unsigned long long a0 = 0ULL, a1 = 0ULL, a2 = 0ULL, a3 = 0ULL;
#pragma unroll
        for (int q = 0; q < 24; q++) {
            ulonglong2 hv = hs2[q];               // 16B broadcast LDS
            if (q & 1) { fma2(a2, hv.x, wr[q].x); fma2(a3, hv.y, wr[q].y); }
            else       { fma2(a0, hv.x, wr[q].x); fma2(a1, hv.y, wr[q].y); }
        }
#pragma unroll
        for (int q = 0; q < 8; q++) {
            ulonglong2 hv = hs2[24 + q];
            ulonglong2 wv = WqS[q * 512 + t];     // conflict-free LDS.128
            if (q & 1) { fma2(a2, hv.x, wv.x); fma2(a3, hv.y, wv.y); }
            else       { fma2(a0, hv.x, wv.x); fma2(a1, hv.y, wv.y); }
        }
        float2 p0 = unpack2(a0), p1 = unpack2(a1), p2 = unpack2(a2), p3 = unpack2(a3);
        float gate = ((p0.x + p0.y) + (p1.x + p1.y)) +
                     ((p2.x + p2.y) + (p3.x + p3.y)) + xg_cur;
        gs[t] = gate;
        xg_cur = xg_next;
        __syncthreads();

        if (t < HID) {
            float iv = gs[t], fv = gs[HID + t], gv = gs[2 * HID + t], ov = gs[3 * HID + t];
            iv = 1.0f / (1.0f + __expf(-iv));
            fv = 1.0f / (1.0f + __expf(-fv));
            gv = tanhf(gv);
            ov = 1.0f / (1.0f + __expf(-ov));
            c = fv * c + iv * gv;
            float h = ov * tanhf(c);
            hlast = h;
            hs[t] = h;
            out[((size_t)s * BAT + bat) * HID + t] = h;
        }
        __syncthreads();
    }

    if (t < HID) {
        size_t off = (size_t)SEQ * BAT * HID;
        out[off + (size_t)bat * HID + t] = hlast;                      // h_T
        out[off + (size_t)BAT * HID + (size_t)bat * HID + t] = c;      // c_T
    }
}

// ---------------------------------------------------------------------------
extern "C" void kernel_launch(void* const* d_in, const int* in_sizes, int n_in,
                              void* d_out, int out_size) {
    (void)in_sizes; (void)n_in; (void)out_size;
    const float* x  = (const float*)d_in[0];
    const float* V  = (const float*)d_in[1];
    const float* W  = (const float*)d_in[2];
    const float* b  = (const float*)d_in[3];
    const float* b2 = (const float*)d_in[4];
    float* out = (float*)d_out;

    float* xg = nullptr;
    cudaGetSymbolAddress((void**)&xg, g_xg);

    cudaFuncSetAttribute(xg_kernel, cudaFuncAttributeMaxDynamicSharedMemorySize,
                         128 * 1024);
    cudaFuncSetAttribute(lstm_rec_kernel, cudaFuncAttributeMaxDynamicSharedMemorySize,
                         8 * 512 * 16 + (128 + 512) * 4 + 256);

    dim3 gridA(SEQ * BAT / 128, GATES / 128);
    xg_kernel<<<gridA, 256, 128 * 1024>>>(x, V, b, b2, xg);
    lstm_rec_kernel<<<BAT, 512, 8 * 512 * 16 + (128 + 512) * 4 + 256>>>(xg, W, out);
}

// round 4
// speedup vs baseline: 1.6781x; 1.6781x over previous
#include <cuda_runtime.h>
#include <math.h>

#define SEQ 2048
#define BAT 128
#define INP 128
#define HID 128
#define GATES 512   // 4*HID

// 512 MB scratch for the precomputed input contribution xg[s][b][g]
__device__ float g_xg[(size_t)SEQ * BAT * GATES];

// ---------------------------------------------------------------------------
// Packed fp32x2 helpers (Blackwell): two full-precision fp32 ops per instr.
// ---------------------------------------------------------------------------
__device__ __forceinline__ void fma2(unsigned long long& d,
                                     unsigned long long a,
                                     unsigned long long b) {
    asm("fma.rn.f32x2 %0, %1, %2, %0;" : "+l"(d) : "l"(a), "l"(b));
}
__device__ __forceinline__ unsigned long long add2(unsigned long long a,
                                                   unsigned long long b) {
    unsigned long long r;
    asm("add.rn.f32x2 %0, %1, %2;" : "=l"(r) : "l"(a), "l"(b));
    return r;
}
__device__ __forceinline__ float2 unpack2(unsigned long long v) {
    float2 r;
    asm("mov.b64 {%0, %1}, %2;" : "=f"(r.x), "=f"(r.y) : "l"(v));
    return r;
}
__device__ __forceinline__ unsigned long long pack2(float lo, float hi) {
    unsigned long long r;
    asm("mov.b64 %0, {%1, %2};" : "=l"(r) : "f"(lo), "f"(hi));
    return r;
}
__device__ __forceinline__ unsigned long long dup2(float v) {
    unsigned long long r;
    asm("mov.b64 %0, {%1, %1};" : "=l"(r) : "f"(v));
    return r;
}

// ---------------------------------------------------------------------------
// Kernel A: xg[m][g] = sum_k x[m][k] * V[g][k] + b[g] + b2[g]
// M = 262144, N = 512, K = 128 (single K tile).
// CTA tile 64m x 128n, 256 threads, per-thread 4m x 8n (4 n-PAIRS packed in
// u64 accumulators -> only 32 accumulator registers). smem 96 KB, 2 CTAs/SM.
// ---------------------------------------------------------------------------
__global__ __launch_bounds__(256, 2) void xg_kernel(
    const float* __restrict__ x, const float* __restrict__ V,
    const float* __restrict__ b1, const float* __restrict__ b2,
    float* __restrict__ xg)
{
    extern __shared__ unsigned char smraw[];
    float*  As = reinterpret_cast<float*>(smraw);                 // [128][64] f32, 32 KB
    float2* Bs = reinterpret_cast<float2*>(smraw + 128 * 64 * 4); // [128][64] f32x2, 64 KB

    const int tid = threadIdx.x;
    const int m0 = blockIdx.x * 64;
    const int n0 = blockIdx.y * 128;

    // As[k][m] = x[m0+m][k]
#pragma unroll
    for (int i = 0; i < 8; i++) {
        int idx = tid + i * 256;          // 0..2047
        int row = idx & 63;
        int k4  = (idx >> 6) << 2;
        float4 xv = *reinterpret_cast<const float4*>(x + (size_t)(m0 + row) * INP + k4);
        As[(k4 + 0) * 64 + row] = xv.x;
        As[(k4 + 1) * 64 + row] = xv.y;
        As[(k4 + 2) * 64 + row] = xv.z;
        As[(k4 + 3) * 64 + row] = xv.w;
    }
    // Bs[k][p] = (V[n0+2p][k], V[n0+2p+1][k])   (n-pairs)
#pragma unroll
    for (int i = 0; i < 8; i++) {
        int idx = tid + i * 256;
        int p  = idx & 63;
        int k4 = (idx >> 6) << 2;
        float4 v0 = *reinterpret_cast<const float4*>(V + (size_t)(n0 + 2 * p) * INP + k4);
        float4 v1 = *reinterpret_cast<const float4*>(V + (size_t)(n0 + 2 * p + 1) * INP + k4);
        Bs[(k4 + 0) * 64 + p] = make_float2(v0.x, v1.x);
        Bs[(k4 + 1) * 64 + p] = make_float2(v0.y, v1.y);
        Bs[(k4 + 2) * 64 + p] = make_float2(v0.z, v1.z);
        Bs[(k4 + 3) * 64 + p] = make_float2(v0.w, v1.w);
    }
    __syncthreads();

    const int tx = tid & 15;          // n-pair group: pairs pb..pb+3
    const int ty = tid >> 4;          // m group: rows mb..mb+3
    const int mb = ty * 4, pb = tx * 4;

    unsigned long long acc[4][4];
#pragma unroll
    for (int i = 0; i < 4; i++)
#pragma unroll
        for (int j = 0; j < 4; j++) acc[i][j] = 0ULL;

#pragma unroll 4
    for (int k = 0; k < 128; k++) {
        float4 a = *reinterpret_cast<const float4*>(&As[k * 64 + mb]);
        ulonglong2 bA = *reinterpret_cast<const ulonglong2*>(&Bs[k * 64 + pb]);
        ulonglong2 bB = *reinterpret_cast<const ulonglong2*>(&Bs[k * 64 + pb + 2]);
        unsigned long long ad0 = dup2(a.x), ad1 = dup2(a.y),
                           ad2 = dup2(a.z), ad3 = dup2(a.w);
        fma2(acc[0][0], ad0, bA.x); fma2(acc[0][1], ad0, bA.y);
        fma2(acc[0][2], ad0, bB.x); fma2(acc[0][3], ad0, bB.y);
        fma2(acc[1][0], ad1, bA.x); fma2(acc[1][1], ad1, bA.y);
        fma2(acc[1][2], ad1, bB.x); fma2(acc[1][3], ad1, bB.y);
        fma2(acc[2][0], ad2, bA.x); fma2(acc[2][1], ad2, bA.y);
        fma2(acc[2][2], ad2, bB.x); fma2(acc[2][3], ad2, bB.y);
        fma2(acc[3][0], ad3, bA.x); fma2(acc[3][1], ad3, bA.y);
        fma2(acc[3][2], ad3, bB.x); fma2(acc[3][3], ad3, bB.y);
    }

    unsigned long long biasp[4];
#pragma unroll
    for (int j = 0; j < 4; j++) {
        int n = n0 + 2 * (pb + j);
        biasp[j] = pack2(b1[n] + b2[n], b1[n + 1] + b2[n + 1]);
    }

#pragma unroll
    for (int i = 0; i < 4; i++) {
        size_t base = (size_t)(m0 + mb + i) * GATES + n0 + 2 * pb;
        ulonglong2 r0, r1;
        r0.x = add2(acc[i][0], biasp[0]); r0.y = add2(acc[i][1], biasp[1]);
        r1.x = add2(acc[i][2], biasp[2]); r1.y = add2(acc[i][3], biasp[3]);
        *reinterpret_cast<ulonglong2*>(xg + base)     = r0;
        *reinterpret_cast<ulonglong2*>(xg + base + 4) = r1;
    }
}

// ---------------------------------------------------------------------------
// Kernel B: recurrence. One CTA per batch element, 512 threads.
// Thread t: hidden unit j = t>>2, gate group grp = t&3, gate row g = grp*128+j.
// The 4 gates of unit j are lanes 4j..4j+3 (one quad) -> shfl exchange.
// Weights: W[g][0..95] in registers (48 u64 = 96 regs),
//          W[g][96..127] in smem WqS[8][512], stored PRE-PERMUTED so that
//          slot tt holds the row for thread tt's gate -> hot-loop load
//          WqS[q*512 + t] is conflict-free LDS.128 AND fetches W[g].
// Double-buffered h in smem -> ONE __syncthreads per step.
// ---------------------------------------------------------------------------
__global__ __launch_bounds__(512, 1) void lstm_rec_kernel(
    const float* __restrict__ xg, const float* __restrict__ W,
    float* __restrict__ out)
{
    extern __shared__ unsigned char smraw[];
    ulonglong2* WqS = reinterpret_cast<ulonglong2*>(smraw);       // [8][512] = 64 KB
    float* hs = reinterpret_cast<float*>(smraw + 8 * 512 * 16);   // [2][128]

    const int t   = threadIdx.x;
    const int bat = blockIdx.x;
    const int j   = t >> 2;
    const int grp = t & 3;
    const int g   = grp * HID + j;      // this thread's gate row
    const int qb  = (t & 31) & ~3;      // quad base lane

    // W[g][0..95] -> 48 u64 registers
    unsigned long long wr[48];
    const unsigned long long* Wrow =
        reinterpret_cast<const unsigned long long*>(W + (size_t)g * INP);
#pragma unroll
    for (int q = 0; q < 48; q++) wr[q] = Wrow[q];

    // Pre-permuted smem weights: slot tt <- W[gate_of(tt)][96 + 4*kq .. +3]
    for (int idx = t; idx < 8 * 512; idx += 512) {
        int kq = idx >> 9;
        int tt = idx & 511;
        int gt = (tt & 3) * HID + (tt >> 2);    // gate row of thread tt
        WqS[kq * 512 + tt] =
            *reinterpret_cast<const ulonglong2*>(W + (size_t)gt * INP + 96 + kq * 4);
    }
    if (t < HID) { hs[t] = 0.0f; }
    __syncthreads();

    float c = 0.0f, h = 0.0f;
    float xg_cur = xg[(size_t)bat * GATES + g];

    for (int s = 0; s < SEQ; s++) {
        float xg_next = 0.0f;
        if (s + 1 < SEQ)
            xg_next = xg[((size_t)(s + 1) * BAT + bat) * GATES + g];

        const ulonglong2* h2 =
            reinterpret_cast<const ulonglong2*>(hs + (s & 1) * HID);

        unsigned long long a0 = 0ULL, a1 = 0ULL, a2 = 0ULL, a3 = 0ULL;
        // h[0..95] x register weights (24 ulonglong2 h-chunks)
#pragma unroll
        for (int q = 0; q < 24; q += 2) {
            ulonglong2 hA = h2[q];
            ulonglong2 hB = h2[q + 1];
            fma2(a0, hA.x, wr[2 * q + 0]);
            fma2(a1, hA.y, wr[2 * q + 1]);
            fma2(a2, hB.x, wr[2 * q + 2]);
            fma2(a3, hB.y, wr[2 * q + 3]);
        }
        // h[96..127] x smem weights (pre-permuted, conflict-free)
#pragma unroll
        for (int q = 0; q < 8; q++) {
            ulonglong2 hv = h2[24 + q];
            ulonglong2 wv = WqS[q * 512 + t];
            if (q & 1) { fma2(a2, hv.x, wv.x); fma2(a3, hv.y, wv.y); }
            else       { fma2(a0, hv.x, wv.x); fma2(a1, hv.y, wv.y); }
        }
        float2 p0 = unpack2(a0), p1 = unpack2(a1),
               p2 = unpack2(a2), p3 = unpack2(a3);
        float gate = ((p0.x + p0.y) + (p1.x + p1.y)) +
                     ((p2.x + p2.y) + (p3.x + p3.y)) + xg_cur;
        xg_cur = xg_next;

        // own activation: grp 0,1,3 -> sigmoid ; grp 2 -> tanh
        float act = (grp == 2) ? tanhf(gate)
                               : (1.0f / (1.0f + __expf(-gate)));

        float vi = __shfl_sync(0xffffffffu, act, qb + 0);
        float vf = __shfl_sync(0xffffffffu, act, qb + 1);
        float vg = __shfl_sync(0xffffffffu, act, qb + 2);
        float vo = __shfl_sync(0xffffffffu, act, qb + 3);

        c = vf * c + vi * vg;
        h = vo * tanhf(c);

        if (grp == 0) hs[((s + 1) & 1) * HID + j] = h;
        if (grp == 1) out[((size_t)s * BAT + bat) * HID + j] = h;
        __syncthreads();
    }

    if (grp == 0) {
        size_t off = (size_t)SEQ * BAT * HID;
        out[off + (size_t)bat * HID + j] = h;                           // h_T
        out[off + (size_t)BAT * HID + (size_t)bat * HID + j] = c;       // c_T
    }
}

// ---------------------------------------------------------------------------
extern "C" void kernel_launch(void* const* d_in, const int* in_sizes, int n_in,
                              void* d_out, int out_size) {
    (void)in_sizes; (void)n_in; (void)out_size;
    const float* x  = (const float*)d_in[0];
    const float* V  = (const float*)d_in[1];
    const float* W  = (const float*)d_in[2];
    const float* b  = (const float*)d_in[3];
    const float* b2 = (const float*)d_in[4];
    float* out = (float*)d_out;

    float* xg = nullptr;
    cudaGetSymbolAddress((void**)&xg, g_xg);

    cudaFuncSetAttribute(xg_kernel, cudaFuncAttributeMaxDynamicSharedMemorySize,
                         96 * 1024);
    const int smemB = 8 * 512 * 16 + 2 * HID * 4 + 256;
    cudaFuncSetAttribute(lstm_rec_kernel, cudaFuncAttributeMaxDynamicSharedMemorySize,
                         smemB);

    dim3 gridA(SEQ * BAT / 64, GATES / 128);
    xg_kernel<<<gridA, 256, 96 * 1024>>>(x, V, b, b2, xg);
    lstm_rec_kernel<<<BAT, 512, smemB>>>(xg, W, out);
}